// round 1
// baseline (speedup 1.0000x reference)
#include <cuda_runtime.h>
#include <math.h>

// ---------------------------------------------------------------------------
// ToRGB: out = tanh( (x * s[b]) @ k2d + bias ),  s = (w@affine_w + affine_b)/sqrt(512)
// Fold: keff[b,c,o] = s[b,c] * k2d[c,o]  -> out[b,p,o] = tanh(sum_c x[b,p,c]*keff[b,c,o] + bias[o])
// ---------------------------------------------------------------------------

#define B_    8
#define CIN   512
#define WDIM  128
#define COUT  4
#define PIX   (128*128)          // pixels per batch
#define INV_SQRT_CIN 0.04419417382415922f

// scratch for the folded per-batch kernel (8*512*4 floats = 64 KB) — static, no alloc
__device__ float g_keff[B_ * CIN * COUT];

// ---------------------------------------------------------------------------
// Prologue: compute keff. grid=(8), block=(512). ~trivial.
// ---------------------------------------------------------------------------
__global__ void build_keff_kernel(const float* __restrict__ w,
                                  const float* __restrict__ affine_w,
                                  const float* __restrict__ affine_b,
                                  const float* __restrict__ k2d)
{
    const int b = blockIdx.x;
    const int c = threadIdx.x;            // 0..511

    __shared__ float ws[WDIM];
    if (threadIdx.x < WDIM) ws[threadIdx.x] = w[b * WDIM + threadIdx.x];
    __syncthreads();

    float s = affine_b[c];
    #pragma unroll 8
    for (int j = 0; j < WDIM; j++)
        s = fmaf(ws[j], affine_w[j * CIN + c], s);
    s *= INV_SQRT_CIN;

    float4 kk = *reinterpret_cast<const float4*>(k2d + c * COUT);
    float4 o;
    o.x = s * kk.x; o.y = s * kk.y; o.z = s * kk.z; o.w = s * kk.w;
    *reinterpret_cast<float4*>(g_keff + (b * CIN + c) * COUT) = o;
}

// ---------------------------------------------------------------------------
// Main: warp-per-pixel streaming contraction. HBM-bound.
// grid = (BLOCKS_PER_BATCH, 8), block = 256 (8 warps).
// Each warp handles PIX / (BLOCKS_PER_BATCH*8) sequential pixels, 2 per iter.
// ---------------------------------------------------------------------------
#define BLOCKS_PER_BATCH 256
#define WARPS_PER_BLOCK  8
#define PIX_PER_BLOCK    (PIX / BLOCKS_PER_BATCH)              // 64
#define PIX_PER_WARP     (PIX_PER_BLOCK / WARPS_PER_BLOCK)     // 8

__global__ void __launch_bounds__(256)
torgb_main_kernel(const float* __restrict__ x,
                  const float* __restrict__ bias,
                  float* __restrict__ out)
{
    const int b    = blockIdx.y;
    const int warp = threadIdx.x >> 5;
    const int lane = threadIdx.x & 31;

    // ---- hoist this lane's 16 channels of keff into registers (once) ----
    // lane handles channels c = lane*4 + j + i*128, i in [0,4), j in [0,4)
    const float* keff = g_keff + b * CIN * COUT;
    float kw[4][4][4];  // [i][j][o]
    #pragma unroll
    for (int i = 0; i < 4; i++) {
        const int cbase = lane * 4 + i * 128;
        #pragma unroll
        for (int j = 0; j < 4; j++) {
            float4 kv = *reinterpret_cast<const float4*>(keff + (cbase + j) * COUT);
            kw[i][j][0] = kv.x; kw[i][j][1] = kv.y; kw[i][j][2] = kv.z; kw[i][j][3] = kv.w;
        }
    }

    const float4 bv = *reinterpret_cast<const float4*>(bias);

    const int pix0 = blockIdx.x * PIX_PER_BLOCK + warp * PIX_PER_WARP;
    const float* xbase = x + ((long long)b * PIX + pix0) * CIN;
    float*       obase = out + ((long long)b * PIX + pix0) * COUT;

    // ---- 2 pixels per iteration for MLP=8 LDG.128 per lane ----
    #pragma unroll
    for (int p = 0; p < PIX_PER_WARP; p += 2) {
        const float* xp0 = xbase + (p + 0) * CIN + lane * 4;
        const float* xp1 = xbase + (p + 1) * CIN + lane * 4;

        float4 a[4], c[4];
        #pragma unroll
        for (int i = 0; i < 4; i++) a[i] = *reinterpret_cast<const float4*>(xp0 + i * 128);
        #pragma unroll
        for (int i = 0; i < 4; i++) c[i] = *reinterpret_cast<const float4*>(xp1 + i * 128);

        float acc0[4] = {0.f, 0.f, 0.f, 0.f};
        float acc1[4] = {0.f, 0.f, 0.f, 0.f};

        #pragma unroll
        for (int i = 0; i < 4; i++) {
            const float av[4] = {a[i].x, a[i].y, a[i].z, a[i].w};
            const float cv[4] = {c[i].x, c[i].y, c[i].z, c[i].w};
            #pragma unroll
            for (int j = 0; j < 4; j++) {
                #pragma unroll
                for (int o = 0; o < 4; o++) {
                    acc0[o] = fmaf(av[j], kw[i][j][o], acc0[o]);
                    acc1[o] = fmaf(cv[j], kw[i][j][o], acc1[o]);
                }
            }
        }

        // ---- warp butterfly reduce (full sums land in every lane; lane 0 writes) ----
        #pragma unroll
        for (int o = 0; o < 4; o++) {
            #pragma unroll
            for (int off = 16; off > 0; off >>= 1) {
                acc0[o] += __shfl_xor_sync(0xffffffffu, acc0[o], off);
                acc1[o] += __shfl_xor_sync(0xffffffffu, acc1[o], off);
            }
        }

        if (lane == 0) {
            float4 r0, r1;
            r0.x = tanhf(acc0[0] + bv.x); r0.y = tanhf(acc0[1] + bv.y);
            r0.z = tanhf(acc0[2] + bv.z); r0.w = tanhf(acc0[3] + bv.w);
            r1.x = tanhf(acc1[0] + bv.x); r1.y = tanhf(acc1[1] + bv.y);
            r1.z = tanhf(acc1[2] + bv.z); r1.w = tanhf(acc1[3] + bv.w);
            *reinterpret_cast<float4*>(obase + (p + 0) * COUT) = r0;
            *reinterpret_cast<float4*>(obase + (p + 1) * COUT) = r1;
        }
    }
}

// ---------------------------------------------------------------------------
// kernel_launch: inputs in setup_inputs() order:
//   d_in[0] = x        [8,128,128,512] f32
//   d_in[1] = w        [8,128]         f32
//   d_in[2] = affine_w [128,512]       f32
//   d_in[3] = affine_b [512]           f32
//   d_in[4] = kernel   [1,1,512,4]     f32
//   d_in[5] = bias     [4]             f32
// out: [8,128,128,4] f32
// ---------------------------------------------------------------------------
extern "C" void kernel_launch(void* const* d_in, const int* in_sizes, int n_in,
                              void* d_out, int out_size)
{
    const float* x        = (const float*)d_in[0];
    const float* w        = (const float*)d_in[1];
    const float* affine_w = (const float*)d_in[2];
    const float* affine_b = (const float*)d_in[3];
    const float* k2d      = (const float*)d_in[4];
    const float* bias     = (const float*)d_in[5];
    float*       out      = (float*)d_out;

    build_keff_kernel<<<B_, CIN>>>(w, affine_w, affine_b, k2d);

    dim3 grid(BLOCKS_PER_BATCH, B_);
    torgb_main_kernel<<<grid, 256>>>(x, bias, out);
}

// round 2
// speedup vs baseline: 1.5188x; 1.5188x over previous
#include <cuda_runtime.h>
#include <math.h>

// ---------------------------------------------------------------------------
// ToRGB: out = tanh( (x * s[b]) @ k2d + bias ),  s = (w@affine_w + affine_b)/sqrt(512)
// Fold: keff[b,c,o] = s[b,c] * k2d[c,o]
// ---------------------------------------------------------------------------

#define B_    8
#define CIN   512
#define WDIM  128
#define COUT  4
#define PIX   (128*128)
#define INV_SQRT_CIN 0.04419417382415922f

// folded per-batch kernel, stored PERMUTED for conflict-free smem reads:
// index = (i*4 + j)*32 + lane   where channel c = lane*4 + j + i*128
__device__ float4 g_keff[B_ * CIN];

// ---------------------------------------------------------------------------
// Prologue: grid=(8 batches, 4 channel-chunks), block=(128, 4 j-slices).
// Each thread sums 32 of the 128 j's; smem reduce; slice 0 finalizes + writes
// in permuted layout.
// ---------------------------------------------------------------------------
__global__ void build_keff_kernel(const float* __restrict__ w,
                                  const float* __restrict__ affine_w,
                                  const float* __restrict__ affine_b,
                                  const float* __restrict__ k2d)
{
    const int b  = blockIdx.x;
    const int c  = blockIdx.y * 128 + threadIdx.x;
    const int js = threadIdx.y;                       // 0..3

    __shared__ float ws[WDIM];
    __shared__ float part[3][128];

    const int tid = threadIdx.y * 128 + threadIdx.x;
    if (tid < WDIM) ws[tid] = w[b * WDIM + tid];
    __syncthreads();

    float s = 0.f;
    const int j0 = js * 32;
    #pragma unroll 8
    for (int j = j0; j < j0 + 32; j++)
        s = fmaf(ws[j], affine_w[j * CIN + c], s);

    if (js > 0) part[js - 1][threadIdx.x] = s;
    __syncthreads();

    if (js == 0) {
        s += part[0][threadIdx.x] + part[1][threadIdx.x] + part[2][threadIdx.x];
        s = (s + affine_b[c]) * INV_SQRT_CIN;
        float4 kk = *reinterpret_cast<const float4*>(k2d + c * COUT);
        float4 o;
        o.x = s * kk.x; o.y = s * kk.y; o.z = s * kk.z; o.w = s * kk.w;
        // permute: c = lane*4 + j + i*128  ->  idx = (i*4 + j)*32 + lane
        const int i = c >> 7, r = c & 127, lane = r >> 2, jj = r & 3;
        g_keff[b * CIN + (i * 4 + jj) * 32 + lane] = o;
    }
}

// ---------------------------------------------------------------------------
// Packed pair reduction step: reduces TWO independent lane-sums with ONE
// shuffle. After the step, 'a'-partials live where lo==true, 'b' where false.
// ---------------------------------------------------------------------------
__device__ __forceinline__ float pairstep(float a, float b, bool lo, int off)
{
    float send = lo ? b : a;
    float recv = __shfl_xor_sync(0xffffffffu, send, off);
    return (lo ? a : b) + recv;
}

// ---------------------------------------------------------------------------
// Main: warp-per-pixel streaming contraction, keff in smem (permuted layout).
// grid = (256, 8), block = 256 (8 warps), 4 CTAs/SM.
// ---------------------------------------------------------------------------
#define BLOCKS_PER_BATCH 256
#define PIX_PER_BLOCK    (PIX / BLOCKS_PER_BATCH)   // 64
#define PIX_PER_WARP     (PIX_PER_BLOCK / 8)        // 8

__global__ void __launch_bounds__(256, 4)
torgb_main_kernel(const float* __restrict__ x,
                  const float* __restrict__ bias,
                  float* __restrict__ out)
{
    const int b    = blockIdx.y;
    const int warp = threadIdx.x >> 5;
    const int lane = threadIdx.x & 31;

    __shared__ float4 kws[CIN];   // 8 KB

    // cooperative fill (coalesced LDG.128 -> conflict-free STS.128)
    {
        const float4* gk = g_keff + b * CIN;
        kws[threadIdx.x]       = gk[threadIdx.x];
        kws[threadIdx.x + 256] = gk[threadIdx.x + 256];
    }
    __syncthreads();

    // per-lane smem base: reads kws[(i*4+j)*32 + lane] via immediate offsets
    const float4* kwl = kws + lane;

    // Each lane's final reduced slot is fixed: seg = lane>>2 (only lanes with
    // lane%4==0 store).  p_off = bit4, o = bit2*2 + bit3.
    const int  seg    = lane >> 2;
    const int  p_off  = (lane >> 4) & 1;
    const int  o_idx  = (((lane >> 2) & 1) << 1) | ((lane >> 3) & 1);
    const bool storer = (lane & 3) == 0;
    const float mybias = storer ? bias[o_idx] : 0.f;
    (void)seg;

    const int pix0 = blockIdx.x * PIX_PER_BLOCK + warp * PIX_PER_WARP;
    const float* xbase = x + ((long long)(b * PIX + pix0)) * CIN + lane * 4;
    float*       myout = out + ((long long)(b * PIX + pix0)) * COUT + p_off * COUT + o_idx;

    const bool lo16 = lane < 16;
    const bool lo8  = (lane & 8) == 0;
    const bool lo4  = (lane & 4) == 0;

    #pragma unroll 1
    for (int p = 0; p < PIX_PER_WARP; p += 2) {
        const float* xp0 = xbase + (long long)p * CIN;
        const float* xp1 = xp0 + CIN;

        float4 a[4], c4[4];
        #pragma unroll
        for (int i = 0; i < 4; i++) a[i]  = __ldcs(reinterpret_cast<const float4*>(xp0 + i * 128));
        #pragma unroll
        for (int i = 0; i < 4; i++) c4[i] = __ldcs(reinterpret_cast<const float4*>(xp1 + i * 128));

        float v0 = 0.f, v1 = 0.f, v2 = 0.f, v3 = 0.f;
        float v4 = 0.f, v5 = 0.f, v6 = 0.f, v7 = 0.f;

        #pragma unroll
        for (int i = 0; i < 4; i++) {
            const float av[4] = {a[i].x,  a[i].y,  a[i].z,  a[i].w};
            const float cv[4] = {c4[i].x, c4[i].y, c4[i].z, c4[i].w};
            #pragma unroll
            for (int j = 0; j < 4; j++) {
                const float4 k = kwl[(i * 4 + j) * 32];   // LDS.128, imm offset
                v0 = fmaf(av[j], k.x, v0);
                v1 = fmaf(av[j], k.y, v1);
                v2 = fmaf(av[j], k.z, v2);
                v3 = fmaf(av[j], k.w, v3);
                v4 = fmaf(cv[j], k.x, v4);
                v5 = fmaf(cv[j], k.y, v5);
                v6 = fmaf(cv[j], k.z, v6);
                v7 = fmaf(cv[j], k.w, v7);
            }
        }

        // packed butterfly: 8 sums in 9 shuffles
        float r0 = pairstep(v0, v4, lo16, 16);
        float r1 = pairstep(v1, v5, lo16, 16);
        float r2 = pairstep(v2, v6, lo16, 16);
        float r3 = pairstep(v3, v7, lo16, 16);

        float s0 = pairstep(r0, r1, lo8, 8);
        float s1 = pairstep(r2, r3, lo8, 8);

        float t  = pairstep(s0, s1, lo4, 4);
        t += __shfl_xor_sync(0xffffffffu, t, 2);
        t += __shfl_xor_sync(0xffffffffu, t, 1);

        if (storer)
            myout[(long long)p * COUT] = tanhf(t + mybias);
    }
}

// ---------------------------------------------------------------------------
// inputs: x[8,128,128,512], w[8,128], affine_w[128,512], affine_b[512],
//         kernel[1,1,512,4], bias[4]  -> out[8,128,128,4] f32
// ---------------------------------------------------------------------------
extern "C" void kernel_launch(void* const* d_in, const int* in_sizes, int n_in,
                              void* d_out, int out_size)
{
    const float* x        = (const float*)d_in[0];
    const float* w        = (const float*)d_in[1];
    const float* affine_w = (const float*)d_in[2];
    const float* affine_b = (const float*)d_in[3];
    const float* k2d      = (const float*)d_in[4];
    const float* bias     = (const float*)d_in[5];
    float*       out      = (float*)d_out;

    dim3 pgrid(B_, 4), pblock(128, 4);
    build_keff_kernel<<<pgrid, pblock>>>(w, affine_w, affine_b, k2d);

    dim3 grid(BLOCKS_PER_BATCH, B_);
    torgb_main_kernel<<<grid, 256>>>(x, bias, out);
}

// round 3
// speedup vs baseline: 1.5285x; 1.0064x over previous
#include <cuda_runtime.h>
#include <math.h>

// ---------------------------------------------------------------------------
// ToRGB: out = tanh( (x * s[b]) @ k2d + bias ),  s = (w@affine_w + affine_b)/sqrt(512)
// Fold: keff[b,c,o] = s[b,c] * k2d[c,o]
// ---------------------------------------------------------------------------

#define B_    8
#define CIN   512
#define WDIM  128
#define COUT  4
#define PIX   (128*128)
#define INV_SQRT_CIN 0.04419417382415922f

// folded per-batch kernel, PERMUTED: idx = (i*4 + j)*32 + lane, c = lane*4 + j + i*128
__device__ float4 g_keff[B_ * CIN];

// ---------------------------------------------------------------------------
// Prologue: grid=(8,4), block=(128,4). Split 128-dot over 4 j-slices.
// ---------------------------------------------------------------------------
__global__ void build_keff_kernel(const float* __restrict__ w,
                                  const float* __restrict__ affine_w,
                                  const float* __restrict__ affine_b,
                                  const float* __restrict__ k2d)
{
    const int b  = blockIdx.x;
    const int c  = blockIdx.y * 128 + threadIdx.x;
    const int js = threadIdx.y;

    __shared__ float ws[WDIM];
    __shared__ float part[3][128];

    const int tid = threadIdx.y * 128 + threadIdx.x;
    if (tid < WDIM) ws[tid] = w[b * WDIM + tid];
    __syncthreads();

    float s = 0.f;
    const int j0 = js * 32;
    #pragma unroll 8
    for (int j = j0; j < j0 + 32; j++)
        s = fmaf(ws[j], affine_w[j * CIN + c], s);

    if (js > 0) part[js - 1][threadIdx.x] = s;
    __syncthreads();

    if (js == 0) {
        s += part[0][threadIdx.x] + part[1][threadIdx.x] + part[2][threadIdx.x];
        s = (s + affine_b[c]) * INV_SQRT_CIN;
        float4 kk = *reinterpret_cast<const float4*>(k2d + c * COUT);
        float4 o;
        o.x = s * kk.x; o.y = s * kk.y; o.z = s * kk.z; o.w = s * kk.w;
        const int i = c >> 7, r = c & 127, lane = r >> 2, jj = r & 3;
        g_keff[b * CIN + (i * 4 + jj) * 32 + lane] = o;
    }
}

// Packed pair reduction: reduce TWO independent lane-sums with ONE shuffle.
// Lanes where lo==true end up holding the 'a' chain; else the 'b' chain.
__device__ __forceinline__ float pairstep(float a, float b, bool lo, int off)
{
    float send = lo ? b : a;
    float recv = __shfl_xor_sync(0xffffffffu, send, off);
    return (lo ? a : b) + recv;
}

// ---------------------------------------------------------------------------
// Main: warp handles 8 pixels as 2 macro-iterations of a 4-pixel tile.
// grid = (256, 8), block = 256 (8 warps), 4 CTAs/SM.
// ---------------------------------------------------------------------------
#define BLOCKS_PER_BATCH 256
#define PIX_PER_BLOCK    (PIX / BLOCKS_PER_BATCH)   // 64
#define PIX_PER_WARP     (PIX_PER_BLOCK / 8)        // 8

__global__ void __launch_bounds__(256, 4)
torgb_main_kernel(const float* __restrict__ x,
                  const float* __restrict__ bias,
                  float* __restrict__ out)
{
    const int b    = blockIdx.y;
    const int warp = threadIdx.x >> 5;
    const int lane = threadIdx.x & 31;

    __shared__ float4 kws[CIN];   // 8 KB

    {
        const float4* gk = g_keff + b * CIN;
        kws[threadIdx.x]       = gk[threadIdx.x];
        kws[threadIdx.x + 256] = gk[threadIdx.x + 256];
    }
    __syncthreads();

    const float4* kwl = kws + lane;

    // Final packed-reduce slot: lane l (even) holds value idx=(l>>1)&15,
    // which is pixel (idx>>2), output (idx&3).
    const int  idx    = (lane >> 1) & 15;
    const int  o_idx  = idx & 3;
    const bool storer = (lane & 1) == 0;
    const float mybias = bias[o_idx];

    const bool lo16 = (lane & 16) == 0;
    const bool lo8  = (lane & 8)  == 0;
    const bool lo4  = (lane & 4)  == 0;
    const bool lo2  = (lane & 2)  == 0;

    const int pix0 = blockIdx.x * PIX_PER_BLOCK + warp * PIX_PER_WARP;
    const float* xbase = x + ((long long)(b * PIX + pix0)) * CIN + lane * 4;
    float*       obase = out + ((long long)(b * PIX + pix0)) * COUT;

    #pragma unroll 1
    for (int pt = 0; pt < PIX_PER_WARP; pt += 4) {
        const float* xp = xbase + (long long)pt * CIN;

        float v[16];
        #pragma unroll
        for (int q = 0; q < 16; q++) v[q] = 0.f;

        #pragma unroll
        for (int i = 0; i < 4; i++) {
            // 4 pixels' data at channel-group i: 4 independent LDG.128
            float4 a0 = __ldcs(reinterpret_cast<const float4*>(xp + 0 * CIN + i * 128));
            float4 a1 = __ldcs(reinterpret_cast<const float4*>(xp + 1 * CIN + i * 128));
            float4 a2 = __ldcs(reinterpret_cast<const float4*>(xp + 2 * CIN + i * 128));
            float4 a3 = __ldcs(reinterpret_cast<const float4*>(xp + 3 * CIN + i * 128));

            // 4 k-vectors for this group (LDS.128, immediate offsets)
            float4 k0 = kwl[(i * 4 + 0) * 32];
            float4 k1 = kwl[(i * 4 + 1) * 32];
            float4 k2 = kwl[(i * 4 + 2) * 32];
            float4 k3 = kwl[(i * 4 + 3) * 32];

            const float4 ap[4] = {a0, a1, a2, a3};
            const float4 kp[4] = {k0, k1, k2, k3};

            #pragma unroll
            for (int p = 0; p < 4; p++) {
                const float av[4] = {ap[p].x, ap[p].y, ap[p].z, ap[p].w};
                #pragma unroll
                for (int j = 0; j < 4; j++) {
                    v[p * 4 + 0] = fmaf(av[j], kp[j].x, v[p * 4 + 0]);
                    v[p * 4 + 1] = fmaf(av[j], kp[j].y, v[p * 4 + 1]);
                    v[p * 4 + 2] = fmaf(av[j], kp[j].z, v[p * 4 + 2]);
                    v[p * 4 + 3] = fmaf(av[j], kp[j].w, v[p * 4 + 3]);
                }
            }
        }

        // ---- packed butterfly: 16 sums in 16 shuffles ----
        float r0 = pairstep(v[0], v[8],  lo16, 16);
        float r1 = pairstep(v[1], v[9],  lo16, 16);
        float r2 = pairstep(v[2], v[10], lo16, 16);
        float r3 = pairstep(v[3], v[11], lo16, 16);
        float r4 = pairstep(v[4], v[12], lo16, 16);
        float r5 = pairstep(v[5], v[13], lo16, 16);
        float r6 = pairstep(v[6], v[14], lo16, 16);
        float r7 = pairstep(v[7], v[15], lo16, 16);

        float s0 = pairstep(r0, r4, lo8, 8);
        float s1 = pairstep(r1, r5, lo8, 8);
        float s2 = pairstep(r2, r6, lo8, 8);
        float s3 = pairstep(r3, r7, lo8, 8);

        float t0 = pairstep(s0, s2, lo4, 4);
        float t1 = pairstep(s1, s3, lo4, 4);

        float u = pairstep(t0, t1, lo2, 2);
        u += __shfl_xor_sync(0xffffffffu, u, 1);

        // lane l (even) holds value idx=(l>>1): pixel idx>>2, out idx&3
        if (storer)
            obase[(long long)pt * COUT + idx] = tanhf(u + mybias);
    }
}

// ---------------------------------------------------------------------------
// inputs: x[8,128,128,512], w[8,128], affine_w[128,512], affine_b[512],
//         kernel[1,1,512,4], bias[4]  -> out[8,128,128,4] f32
// ---------------------------------------------------------------------------
extern "C" void kernel_launch(void* const* d_in, const int* in_sizes, int n_in,
                              void* d_out, int out_size)
{
    const float* x        = (const float*)d_in[0];
    const float* w        = (const float*)d_in[1];
    const float* affine_w = (const float*)d_in[2];
    const float* affine_b = (const float*)d_in[3];
    const float* k2d      = (const float*)d_in[4];
    const float* bias     = (const float*)d_in[5];
    float*       out      = (float*)d_out;

    dim3 pgrid(B_, 4), pblock(128, 4);
    build_keff_kernel<<<pgrid, pblock>>>(w, affine_w, affine_b, k2d);

    dim3 grid(BLOCKS_PER_BATCH, B_);
    torgb_main_kernel<<<grid, 256>>>(x, bias, out);
}